// round 5
// baseline (speedup 1.0000x reference)
#include <cuda_runtime.h>
#include <cuda_bf16.h>
#include <math.h>

// EMDLoss: mean over (b,n) of min_m ||pred[b,n]-target[b,m]||, B=32, N=M=4096, d=3.
// Exact spatial-grid nearest-neighbor:
//   targets binned per batch into 32^3 cells over [-4,4]^3 (out-of-range clamps to
//   boundary cells). Per pred: expanding Chebyshev shells; stop when best d^2 <=
//   squared distance to the nearest NON-boundary face of the examined cube
//   (boundary faces => +inf, so clamped points are handled exactly).

#define EMD_B 32
#define EMD_N 4096
#define EMD_M 4096

#define G      32
#define NCELLS (G * G * G)
#define XMIN   (-4.0f)
#define H      0.25f
#define INVH   4.0f

#define THREADS 256

__device__ int    g_cnt[EMD_B][NCELLS];     // 4 MB
__device__ int    g_cur[EMD_B][NCELLS];     // 4 MB
__device__ int2   g_meta[EMD_B][NCELLS];    // 8 MB  (offset, count)
__device__ float4 g_pts[EMD_B * EMD_M];     // 2 MB  binned targets

__device__ __forceinline__ int cell_of(float v)
{
    int c = (int)floorf((v - XMIN) * INVH);
    return min(max(c, 0), G - 1);
}

// ---------------------------------------------------------------- zero bins
__global__ void __launch_bounds__(THREADS)
zero_kernel()
{
    const int i = blockIdx.x * THREADS + threadIdx.x;   // 0 .. B*NCELLS-1
    ((int*)g_cnt)[i] = 0;
    ((int*)g_cur)[i] = 0;
}

// ---------------------------------------------------------------- count
__global__ void __launch_bounds__(THREADS)
count_kernel(const float* __restrict__ target)
{
    const int i = blockIdx.x * THREADS + threadIdx.x;   // 0 .. B*M-1
    const int b = i >> 12;
    const float* t = target + (size_t)i * 3;
    const int cx = cell_of(t[0]);
    const int cy = cell_of(t[1]);
    const int cz = cell_of(t[2]);
    atomicAdd(&g_cnt[b][(cz * G + cy) * G + cx], 1);
}

// ---------------------------------------------------------------- per-batch CSR scan
// 32 blocks (one per batch) x 1024 threads; each thread owns 32 consecutive cells.
__global__ void __launch_bounds__(1024)
scan_kernel()
{
    __shared__ int part[1024];
    const int b = blockIdx.x;
    const int t = threadIdx.x;
    const int base_cell = t * 32;

    int local[32];
    int sum = 0;
    #pragma unroll
    for (int i = 0; i < 32; i++) {
        local[i] = g_cnt[b][base_cell + i];
        sum += local[i];
    }
    part[t] = sum;
    __syncthreads();

    // inclusive Hillis-Steele scan over 1024 partials
    #pragma unroll
    for (int off = 1; off < 1024; off <<= 1) {
        int v = (t >= off) ? part[t - off] : 0;
        __syncthreads();
        part[t] += v;
        __syncthreads();
    }
    int run = b * EMD_M + (t ? part[t - 1] : 0);   // exclusive prefix + batch base

    #pragma unroll
    for (int i = 0; i < 32; i++) {
        g_meta[b][base_cell + i] = make_int2(run, local[i]);
        run += local[i];
    }
}

// ---------------------------------------------------------------- scatter
__global__ void __launch_bounds__(THREADS)
scatter_kernel(const float* __restrict__ target)
{
    const int i = blockIdx.x * THREADS + threadIdx.x;
    const int b = i >> 12;
    const float* t = target + (size_t)i * 3;
    const float x = t[0], y = t[1], z = t[2];
    const int cell = (cell_of(z) * G + cell_of(y)) * G + cell_of(x);
    const int slot = g_meta[b][cell].x + atomicAdd(&g_cur[b][cell], 1);
    g_pts[slot] = make_float4(x, y, z, 0.0f);
}

// ---------------------------------------------------------------- search + mean
__global__ void __launch_bounds__(THREADS)
search_kernel(const float* __restrict__ pred,
              float* __restrict__ out)
{
    __shared__ float wsum[THREADS / 32];

    const int i = blockIdx.x * THREADS + threadIdx.x;   // 0 .. B*N-1
    const int b = i >> 12;
    const float* pp = pred + (size_t)i * 3;
    const float px = pp[0], py = pp[1], pz = pp[2];
    const int cx = cell_of(px), cy = cell_of(py), cz = cell_of(pz);

    const int2* __restrict__ meta = g_meta[b];

    float best = 3.4e38f;

    for (int k = 0; k < G; k++) {
        const int zlo = max(cz - k, 0), zhi = min(cz + k, G - 1);
        const int ylo = max(cy - k, 0), yhi = min(cy + k, G - 1);
        const int xlo = max(cx - k, 0), xhi = min(cx + k, G - 1);

        for (int z = zlo; z <= zhi; z++) {
            const bool fz = (z - cz == k) || (cz - z == k);
            for (int y = ylo; y <= yhi; y++) {
                const bool fzy = fz || (y - cy == k) || (cy - y == k);
                for (int x = xlo; x <= xhi; x++) {
                    if (!fzy && (x - cx != k) && (cx - x != k)) continue;  // shell surface only
                    const int2 oc = meta[(z * G + y) * G + x];
                    for (int tt = 0; tt < oc.y; tt++) {
                        const float4 q = g_pts[oc.x + tt];
                        const float dx = px - q.x;
                        const float dy = py - q.y;
                        const float dz = pz - q.z;
                        const float d2 = fmaf(dx, dx, fmaf(dy, dy, dz * dz));
                        best = fminf(best, d2);
                    }
                }
            }
        }

        // exact stopping bound: nearest non-boundary face of the examined cube
        float bnd = 3.4e38f;
        if (cx - k > 0)     bnd = fminf(bnd, px - (XMIN + (float)(cx - k) * H));
        if (cx + k < G - 1) bnd = fminf(bnd, (XMIN + (float)(cx + k + 1) * H) - px);
        if (cy - k > 0)     bnd = fminf(bnd, py - (XMIN + (float)(cy - k) * H));
        if (cy + k < G - 1) bnd = fminf(bnd, (XMIN + (float)(cy + k + 1) * H) - py);
        if (cz - k > 0)     bnd = fminf(bnd, pz - (XMIN + (float)(cz - k) * H));
        if (cz + k < G - 1) bnd = fminf(bnd, (XMIN + (float)(cz + k + 1) * H) - pz);
        bnd = fmaxf(bnd, 0.0f);
        if (best <= bnd * bnd) break;
    }

    const float d = sqrtf(fmaxf(best, 0.0f));
    float val = d * (1.0f / ((float)EMD_B * (float)EMD_N));

    #pragma unroll
    for (int o = 16; o; o >>= 1)
        val += __shfl_xor_sync(0xffffffffu, val, o);
    if ((threadIdx.x & 31) == 0)
        wsum[threadIdx.x >> 5] = val;
    __syncthreads();

    if (threadIdx.x < (THREADS / 32)) {
        float v = wsum[threadIdx.x];
        #pragma unroll
        for (int o = (THREADS / 64); o; o >>= 1)
            v += __shfl_xor_sync(0xffu, v, o);
        if (threadIdx.x == 0)
            atomicAdd(out, v);
    }
}

extern "C" void kernel_launch(void* const* d_in, const int* in_sizes, int n_in,
                              void* d_out, int out_size)
{
    const float* pred   = (const float*)d_in[0];
    const float* target = (const float*)d_in[1];
    float* out = (float*)d_out;

    cudaMemsetAsync(out, 0, sizeof(float));

    const int nbin_threads = EMD_B * NCELLS;            // 1,048,576
    zero_kernel<<<nbin_threads / THREADS, THREADS>>>();

    const int npts = EMD_B * EMD_M;                     // 131,072
    count_kernel<<<npts / THREADS, THREADS>>>(target);
    scan_kernel<<<EMD_B, 1024>>>();
    scatter_kernel<<<npts / THREADS, THREADS>>>(target);

    search_kernel<<<EMD_B * EMD_N / THREADS, THREADS>>>(pred, out);
}

// round 6
// speedup vs baseline: 2.5848x; 2.5848x over previous
#include <cuda_runtime.h>
#include <cuda_bf16.h>
#include <math.h>

// EMDLoss: mean over (b,n) of min_m ||pred[b,n]-target[b,m]||, B=32, N=M=4096, d=3.
// Exact grid NN search, ONE WARP PER PRED (warp-uniform rounds, lanes over cells).
// Targets binned per batch into 32^3 cells over [-4,4]^3 (CSR via global 3-stage scan).
// Stopping rule: after scanning the Chebyshev-k cube, any unexamined point lies
// beyond a non-clipped cube face plane; clipped faces contribute +inf. Exact.

#define EMD_B 32
#define EMD_N 4096
#define EMD_M 4096

#define G      32
#define NCELLS (G * G * G)          // 32768 per batch
#define NC_TOT (EMD_B * NCELLS)     // 1,048,576
#define XMIN   (-4.0f)
#define H      0.25f
#define INVH   4.0f

#define THREADS 256
#define SCAN_T  1024
#define SCAN_BLKS (NC_TOT / SCAN_T)  // 1024

__device__ int    g_cnt[NC_TOT];        // per-cell counts
__device__ int    g_cur[NC_TOT];        // scatter cursors
__device__ int    g_off[NC_TOT];        // exclusive offset within scan block
__device__ int    g_bsum[SCAN_BLKS];    // per-block sums -> exclusive block offsets
__device__ int2   g_meta[NC_TOT];       // (global offset, count)
__device__ float4 g_pts[EMD_B * EMD_M]; // binned targets

__device__ __forceinline__ int cell_of(float v)
{
    int c = (int)floorf((v - XMIN) * INVH);
    return min(max(c, 0), G - 1);
}

// ---------------------------------------------------------------- zero
__global__ void __launch_bounds__(THREADS)
zero_kernel()
{
    const int i = blockIdx.x * THREADS + threadIdx.x;
    g_cnt[i] = 0;
    g_cur[i] = 0;
}

// ---------------------------------------------------------------- count
__global__ void __launch_bounds__(THREADS)
count_kernel(const float* __restrict__ target)
{
    const int i = blockIdx.x * THREADS + threadIdx.x;   // 0 .. B*M-1
    const int b = i >> 12;
    const float* t = target + (size_t)i * 3;
    const int cell = (cell_of(t[2]) * G + cell_of(t[1])) * G + cell_of(t[0]);
    atomicAdd(&g_cnt[b * NCELLS + cell], 1);
}

// ---------------------------------------------------------------- scan stage A
__global__ void __launch_bounds__(SCAN_T)
scanA_kernel()
{
    __shared__ int sh[SCAN_T];
    const int t = threadIdx.x;
    const int i = blockIdx.x * SCAN_T + t;
    const int v = g_cnt[i];
    sh[t] = v;
    __syncthreads();
    #pragma unroll
    for (int off = 1; off < SCAN_T; off <<= 1) {
        int u = (t >= off) ? sh[t - off] : 0;
        __syncthreads();
        sh[t] += u;
        __syncthreads();
    }
    g_off[i] = sh[t] - v;                 // exclusive within block
    if (t == SCAN_T - 1)
        g_bsum[blockIdx.x] = sh[t];
}

// ---------------------------------------------------------------- scan stage B
__global__ void __launch_bounds__(SCAN_BLKS)
scanB_kernel()
{
    __shared__ int sh[SCAN_BLKS];
    const int t = threadIdx.x;
    const int v = g_bsum[t];
    sh[t] = v;
    __syncthreads();
    #pragma unroll
    for (int off = 1; off < SCAN_BLKS; off <<= 1) {
        int u = (t >= off) ? sh[t - off] : 0;
        __syncthreads();
        sh[t] += u;
        __syncthreads();
    }
    g_bsum[t] = sh[t] - v;                // exclusive block offset
}

// ---------------------------------------------------------------- scan stage C
__global__ void __launch_bounds__(SCAN_T)
scanC_kernel()
{
    const int i = blockIdx.x * SCAN_T + threadIdx.x;
    g_meta[i] = make_int2(g_off[i] + g_bsum[blockIdx.x], g_cnt[i]);
}

// ---------------------------------------------------------------- scatter
__global__ void __launch_bounds__(THREADS)
scatter_kernel(const float* __restrict__ target)
{
    const int i = blockIdx.x * THREADS + threadIdx.x;
    const int b = i >> 12;
    const float* t = target + (size_t)i * 3;
    const float x = t[0], y = t[1], z = t[2];
    const int cell = b * NCELLS + (cell_of(z) * G + cell_of(y)) * G + cell_of(x);
    const int slot = g_meta[cell].x + atomicAdd(&g_cur[cell], 1);
    g_pts[slot] = make_float4(x, y, z, 0.0f);
}

// ---------------------------------------------------------------- search (warp per pred)
#define SEARCH_T 512
#define WPB (SEARCH_T / 32)      // 16 preds per block

__global__ void __launch_bounds__(SEARCH_T)
search_kernel(const float* __restrict__ pred,
              float* __restrict__ out)
{
    __shared__ float shsum[WPB];

    const int wid  = threadIdx.x >> 5;
    const int lane = threadIdx.x & 31;
    const int p    = blockIdx.x * WPB + wid;     // pred index
    const int b    = p >> 12;

    const float* pp = pred + (size_t)p * 3;
    const float px = pp[0], py = pp[1], pz = pp[2];
    const int cx = cell_of(px), cy = cell_of(py), cz = cell_of(pz);

    const int2*   __restrict__ meta = g_meta + b * NCELLS;
    const float4* __restrict__ pts  = g_pts;

    float best = 3.4e38f;

    for (int k = 1; k <= G; k++) {
        const int side = 2 * k + 1;
        const int ncub = side * side * side;

        for (int c = lane; c < ncub; c += 32) {
            const int dx =  c % side        - k;
            const int dy = (c / side) % side - k;
            const int dz =  c / (side * side) - k;
            const int x = cx + dx, y = cy + dy, z = cz + dz;
            if ((unsigned)x < G && (unsigned)y < G && (unsigned)z < G) {
                const int2 oc = meta[(z * G + y) * G + x];
                for (int tt = 0; tt < oc.y; tt++) {
                    const float4 q = pts[oc.x + tt];
                    const float ddx = px - q.x;
                    const float ddy = py - q.y;
                    const float ddz = pz - q.z;
                    best = fminf(best, fmaf(ddx, ddx, fmaf(ddy, ddy, ddz * ddz)));
                }
            }
        }

        // warp-reduce running best
        #pragma unroll
        for (int o = 16; o; o >>= 1)
            best = fminf(best, __shfl_xor_sync(0xffffffffu, best, o));

        // exact stopping bound: nearest non-clipped cube face plane
        float bnd = 3.4e38f;
        if (cx - k > 0)     bnd = fminf(bnd, px - (XMIN + (float)(cx - k) * H));
        if (cx + k < G - 1) bnd = fminf(bnd, (XMIN + (float)(cx + k + 1) * H) - px);
        if (cy - k > 0)     bnd = fminf(bnd, py - (XMIN + (float)(cy - k) * H));
        if (cy + k < G - 1) bnd = fminf(bnd, (XMIN + (float)(cy + k + 1) * H) - py);
        if (cz - k > 0)     bnd = fminf(bnd, pz - (XMIN + (float)(cz - k) * H));
        if (cz + k < G - 1) bnd = fminf(bnd, (XMIN + (float)(cz + k + 1) * H) - pz);
        bnd = fmaxf(bnd, 0.0f);
        if (best <= bnd * bnd) break;     // bnd==inf when fully clipped -> also breaks
    }

    if (lane == 0)
        shsum[wid] = sqrtf(fmaxf(best, 0.0f)) * (1.0f / ((float)EMD_B * (float)EMD_N));
    __syncthreads();

    if (threadIdx.x < WPB) {
        float v = shsum[threadIdx.x];
        #pragma unroll
        for (int o = WPB / 2; o; o >>= 1)
            v += __shfl_xor_sync((1u << WPB) - 1u, v, o);
        if (threadIdx.x == 0)
            atomicAdd(out, v);
    }
}

extern "C" void kernel_launch(void* const* d_in, const int* in_sizes, int n_in,
                              void* d_out, int out_size)
{
    const float* pred   = (const float*)d_in[0];
    const float* target = (const float*)d_in[1];
    float* out = (float*)d_out;

    cudaMemsetAsync(out, 0, sizeof(float));

    zero_kernel<<<NC_TOT / THREADS, THREADS>>>();

    const int npts = EMD_B * EMD_M;                     // 131,072
    count_kernel<<<npts / THREADS, THREADS>>>(target);

    scanA_kernel<<<SCAN_BLKS, SCAN_T>>>();
    scanB_kernel<<<1, SCAN_BLKS>>>();
    scanC_kernel<<<SCAN_BLKS, SCAN_T>>>();

    scatter_kernel<<<npts / THREADS, THREADS>>>(target);

    search_kernel<<<EMD_B * EMD_N / WPB, SEARCH_T>>>(pred, out);
}